// round 9
// baseline (speedup 1.0000x reference)
#include <cuda_runtime.h>

#define B_   4
#define N_   4096
#define K_   512
#define NT   32                 // children per CTA (= loop length)
#define GRID_X (N_/NT)          // 128
#define GRID_TOTAL (GRID_X*B_)  // 512
#define NTHR 256                // thread owns parents 2*tid, 2*tid+1 (f32x2 lanes)
#define STAGES 16               // cp.async ring depth (rows of A)
#define ROWB (K_*4)             // bytes per A row = 2048
#define EPSF 1e-6f

typedef unsigned long long ull;

__device__ double   g_blkP[GRID_TOTAL];
__device__ double   g_blkC[GRID_TOTAL];
__device__ float    g_blkM[GRID_TOTAL];
__device__ unsigned g_cnt;   // zero-init; atomicInc wrap resets each launch

__device__ __forceinline__ ull pack2(float lo, float hi) {
    ull r; asm("mov.b64 %0, {%1, %2};" : "=l"(r) : "f"(lo), "f"(hi)); return r;
}
__device__ __forceinline__ float2 unpack2(ull v) {
    float2 r; asm("mov.b64 {%0, %1}, %2;" : "=f"(r.x), "=f"(r.y) : "l"(v)); return r;
}
__device__ __forceinline__ ull fma2(ull a, ull b, ull c) {
    ull d; asm("fma.rn.f32x2 %0, %1, %2, %3;" : "=l"(d) : "l"(a), "l"(b), "l"(c)); return d;
}
__device__ __forceinline__ ull mul2(ull a, ull b) {
    ull d; asm("mul.rn.f32x2 %0, %1, %2;" : "=l"(d) : "l"(a), "l"(b)); return d;
}
__device__ __forceinline__ ull add2(ull a, ull b) {
    ull d; asm("add.rn.f32x2 %0, %1, %2;" : "=l"(d) : "l"(a), "l"(b)); return d;
}
__device__ __forceinline__ void lds2(unsigned addr, ull& x, ull& y) {
    asm("ld.shared.v2.b64 {%0, %1}, [%2];" : "=l"(x), "=l"(y) : "r"(addr));
}
__device__ __forceinline__ ull lds64(unsigned addr) {
    ull v; asm("ld.shared.b64 %0, [%1];" : "=l"(v) : "r"(addr)); return v;
}
__device__ __forceinline__ void cp_async8(unsigned saddr, const void* gaddr) {
    asm volatile("cp.async.ca.shared.global [%0], [%1], 8;" :: "r"(saddr), "l"(gaddr));
}
__device__ __forceinline__ void cp_commit() {
    asm volatile("cp.async.commit_group;");
}
__device__ __forceinline__ void cp_wait15() {
    asm volatile("cp.async.wait_group 15;");
}

// symmetric 3x3 inverse of (S + eps*I)
__device__ __forceinline__ void inv3sym(const float* __restrict__ S,
                                        float& i00, float& i01, float& i02,
                                        float& i11, float& i12, float& i22) {
    float s00 = S[0] + EPSF, s01 = S[1], s02 = S[2];
    float s11 = S[4] + EPSF, s12 = S[5];
    float s22 = S[8] + EPSF;
    float c00 = s11 * s22 - s12 * s12;
    float c01 = s02 * s12 - s01 * s22;
    float c02 = s01 * s12 - s02 * s11;
    float c11 = s00 * s22 - s02 * s02;
    float c12 = s01 * s02 - s00 * s12;
    float c22 = s00 * s11 - s01 * s01;
    float det = s00 * c00 + s01 * c01 + s02 * c02;
    float id  = 1.0f / det;
    i00 = c00 * id; i01 = c01 * id; i02 = c02 * id;
    i11 = c11 * id; i12 = c12 * id; i22 = c22 * id;
}

__global__ void __launch_bounds__(NTHR, 3)
loss_kernel(const float* __restrict__ muC, const float* __restrict__ SC,
            const float* __restrict__ muP, const float* __restrict__ SP,
            const float* __restrict__ A,   const float* __restrict__ mask,
            float* __restrict__ out)
{
    // child features (duplicated {v,v}): c0,c1,c2, J00,J11,J22, 2J01,2J02,2J12, m
    __shared__ float shF[NT * 20];
    __shared__ __align__(16) float shA[STAGES * K_];   // 16 x 2KB A-row ring
    __shared__ float redP[8], redC[8];
    __shared__ float sMask;
    __shared__ int   sLast;

    const int b   = blockIdx.y;
    const int n0  = blockIdx.x * NT;
    const int tid = threadIdx.x;
    const int k0  = 2 * tid;

    // ---- start A pipeline immediately: prologue fills 16 rows ----
    unsigned sA = (unsigned)__cvta_generic_to_shared(shA) + tid * 8;
    const float* Arow = A + ((size_t)b * N_ + n0) * K_ + k0;
#pragma unroll
    for (int i = 0; i < STAGES; i++) {
        cp_async8(sA + i * ROWB, Arow + (size_t)i * K_);
        cp_commit();
    }

    // ---- parent-pair features, packed {k0, k1} (9 ull) ----
    float a00, a01, a02, a11, a12, a22;
    float b00, b01, b02, b11, b12, b22;
    inv3sym(SP + (size_t)(b * K_ + k0) * 9,     a00, a01, a02, a11, a12, a22);
    inv3sym(SP + (size_t)(b * K_ + k0 + 1) * 9, b00, b01, b02, b11, b12, b22);
    const float* mpA = muP + (size_t)(b * K_ + k0) * 3;
    const float* mpB = muP + (size_t)(b * K_ + k0 + 1) * 3;
    ull Pn0  = pack2(-mpA[0], -mpB[0]);
    ull Pn1  = pack2(-mpA[1], -mpB[1]);
    ull Pn2  = pack2(-mpA[2], -mpB[2]);
    ull PI00 = pack2(a00, b00);
    ull PI11 = pack2(a11, b11);
    ull PI22 = pack2(a22, b22);
    ull PI01 = pack2(2.f * a01, 2.f * b01);
    ull PI02 = pack2(2.f * a02, 2.f * b02);
    ull PI12 = pack2(2.f * a12, 2.f * b12);

    // ---- child features -> shared, duplicated {v,v} ----
    if (tid < NT) {
        int n = n0 + tid;
        float j00, j01, j02, j11, j12, j22;
        inv3sym(SC + (size_t)(b * N_ + n) * 9, j00, j01, j02, j11, j12, j22);
        const float* mc = muC + (size_t)(b * N_ + n) * 3;
        float m = mask[b * N_ + n];
        float* d = &shF[tid * 20];
        d[0]  = mc[0];      d[1]  = mc[0];
        d[2]  = mc[1];      d[3]  = mc[1];
        d[4]  = mc[2];      d[5]  = mc[2];
        d[6]  = j00;        d[7]  = j00;
        d[8]  = j11;        d[9]  = j11;
        d[10] = j22;        d[11] = j22;
        d[12] = 2.f * j01;  d[13] = 2.f * j01;
        d[14] = 2.f * j02;  d[15] = 2.f * j02;
        d[16] = 2.f * j12;  d[17] = 2.f * j12;
        d[18] = m;          d[19] = m;
    }
    __syncthreads();

    // block mask partial: warp 0, lane i owns child i
    if (tid < 32) {
        float m = shF[tid * 20 + 18];
#pragma unroll
        for (int off = 16; off; off >>= 1)
            m += __shfl_down_sync(0xffffffffu, m, off);
        if (tid == 0) sMask = m;
    }

    unsigned sbase = (unsigned)__cvta_generic_to_shared(shF);

    ull accP = 0ull, accC = 0ull;

#pragma unroll 8
    for (int n = 0; n < NT; ++n) {
        cp_wait15();                       // row n resident (per-thread bytes)
        unsigned slot = sA + (n & (STAGES - 1)) * ROWB;
        ull araw = lds64(slot);            // {A(n,k0), A(n,k1)} already packed
        if (n + STAGES < NT)
            cp_async8(slot, Arow + (size_t)(n + STAGES) * K_);
        cp_commit();                       // commit every iter (may be empty)

        unsigned ad = sbase + n * 80;
        ull Fc0, Fc1, Fc2, FJ00, FJ11, FJ22, FJ01, FJ02, FJ12, Fm;
        lds2(ad,      Fc0,  Fc1 );
        lds2(ad + 16, Fc2,  FJ00);
        lds2(ad + 32, FJ11, FJ22);
        lds2(ad + 48, FJ01, FJ02);
        lds2(ad + 64, FJ12, Fm  );

        ull d0 = add2(Fc0, Pn0);
        ull d1 = add2(Fc1, Pn1);
        ull d2 = add2(Fc2, Pn2);

        ull dd, mp, mc;
        dd = mul2(d0, d0);
        mp = mul2(dd, PI00);      mc = mul2(dd, FJ00);
        dd = mul2(d1, d1);
        mp = fma2(dd, PI11, mp);  mc = fma2(dd, FJ11, mc);
        dd = mul2(d2, d2);
        mp = fma2(dd, PI22, mp);  mc = fma2(dd, FJ22, mc);
        dd = mul2(d0, d1);
        mp = fma2(dd, PI01, mp);  mc = fma2(dd, FJ01, mc);
        dd = mul2(d0, d2);
        mp = fma2(dd, PI02, mp);  mc = fma2(dd, FJ02, mc);
        dd = mul2(d1, d2);
        mp = fma2(dd, PI12, mp);  mc = fma2(dd, FJ12, mc);

        ull am = mul2(araw, Fm);           // {A,A} * mask
        accP = fma2(am, mp, accP);
        accC = fma2(am, mc, accC);
    }

    // ---- in-block reduction ----
    float2 vP = unpack2(accP), vC = unpack2(accC);
    float sp = vP.x + vP.y;
    float sc = vC.x + vC.y;
#pragma unroll
    for (int off = 16; off; off >>= 1) {
        sp += __shfl_down_sync(0xffffffffu, sp, off);
        sc += __shfl_down_sync(0xffffffffu, sc, off);
    }
    int wid = tid >> 5, lane = tid & 31;
    if (lane == 0) { redP[wid] = sp; redC[wid] = sc; }
    __syncthreads();

    const int bid = blockIdx.y * gridDim.x + blockIdx.x;
    if (tid == 0) {
        float tp = 0.f, tc = 0.f;
#pragma unroll
        for (int i = 0; i < 8; i++) { tp += redP[i]; tc += redC[i]; }
        g_blkP[bid] = (double)tp;
        g_blkC[bid] = (double)tc;
        g_blkM[bid] = sMask;
        __threadfence();
        unsigned t = atomicInc(&g_cnt, GRID_TOTAL - 1);
        sLast = (t == GRID_TOTAL - 1);
    }
    __syncthreads();

    // ---- last block: final reduction + output ----
    if (sLast) {
        __threadfence();
        __shared__ double fP[8], fC[8];
        __shared__ float  fM[8];
        double p = g_blkP[tid] + g_blkP[tid + NTHR];   // 512 slots
        double c = g_blkC[tid] + g_blkC[tid + NTHR];
        float  m = g_blkM[tid] + g_blkM[tid + NTHR];
#pragma unroll
        for (int off = 16; off; off >>= 1) {
            p += __shfl_down_sync(0xffffffffu, p, off);
            c += __shfl_down_sync(0xffffffffu, c, off);
            m += __shfl_down_sync(0xffffffffu, m, off);
        }
        if (lane == 0) { fP[wid] = p; fC[wid] = c; fM[wid] = m; }
        __syncthreads();
        if (tid == 0) {
            double tp = 0.0, tc = 0.0;
            float  tm = 0.f;
#pragma unroll
            for (int i = 0; i < 8; i++) { tp += fP[i]; tc += fC[i]; tm += fM[i]; }
            double denom = (tm > 1.f) ? (double)tm : 1.0;
            out[0] = (float)((tp + tc) / denom);  // final_loss
            out[1] = (float)(tp / denom);          // dist_p_m
            out[2] = (float)(tc / denom);          // dist_c_m
        }
    }
}

extern "C" void kernel_launch(void* const* d_in, const int* in_sizes, int n_in,
                              void* d_out, int out_size) {
    const float* muC  = (const float*)d_in[0];
    const float* SC   = (const float*)d_in[1];
    const float* muP  = (const float*)d_in[2];
    const float* SP   = (const float*)d_in[3];
    const float* A    = (const float*)d_in[4];
    const float* mask = (const float*)d_in[5];

    dim3 grid(GRID_X, B_);
    loss_kernel<<<grid, NTHR>>>(muC, SC, muP, SP, A, mask, (float*)d_out);
}

// round 11
// speedup vs baseline: 1.1082x; 1.1082x over previous
#include <cuda_runtime.h>

#define B_   4
#define N_   4096
#define K_   512
#define NT   32                 // children per CTA
#define GRID_X (N_/NT)          // 128
#define GRID_TOTAL (GRID_X*B_)  // 512
#define NTHR 256                // thread owns parents 2*tid, 2*tid+1 (f32x2 lanes)
#define ROWB (K_*4)             // 2048 B per A row
#define NCHUNK 4
#define CHUNK_ROWS (NT/NCHUNK)  // 8
#define CHUNK_BYTES (CHUNK_ROWS*ROWB)   // 16384
#define SH_A    0
#define SH_F    (NT*ROWB)               // 65536
#define SH_REDP (SH_F + NT*80)          // 68096
#define SH_REDC (SH_REDP + 32)
#define SH_MASK (SH_REDC + 32)
#define SH_LAST (SH_MASK + 4)
#define SH_MBAR (SH_LAST + 4)           // 4 x 8B mbarriers
#define SMEM_TOTAL (SH_MBAR + 64)
#define EPSF 1e-6f

typedef unsigned long long ull;

__device__ double   g_blkP[GRID_TOTAL];
__device__ double   g_blkC[GRID_TOTAL];
__device__ float    g_blkM[GRID_TOTAL];
__device__ unsigned g_cnt;   // zero-init; atomicInc wrap resets each launch

__device__ __forceinline__ ull pack2(float lo, float hi) {
    ull r; asm("mov.b64 %0, {%1, %2};" : "=l"(r) : "f"(lo), "f"(hi)); return r;
}
__device__ __forceinline__ float2 unpack2(ull v) {
    float2 r; asm("mov.b64 {%0, %1}, %2;" : "=f"(r.x), "=f"(r.y) : "l"(v)); return r;
}
__device__ __forceinline__ ull fma2(ull a, ull b, ull c) {
    ull d; asm("fma.rn.f32x2 %0, %1, %2, %3;" : "=l"(d) : "l"(a), "l"(b), "l"(c)); return d;
}
__device__ __forceinline__ ull mul2(ull a, ull b) {
    ull d; asm("mul.rn.f32x2 %0, %1, %2;" : "=l"(d) : "l"(a), "l"(b)); return d;
}
__device__ __forceinline__ ull add2(ull a, ull b) {
    ull d; asm("add.rn.f32x2 %0, %1, %2;" : "=l"(d) : "l"(a), "l"(b)); return d;
}
__device__ __forceinline__ void lds2(unsigned addr, ull& x, ull& y) {
    asm("ld.shared.v2.b64 {%0, %1}, [%2];" : "=l"(x), "=l"(y) : "r"(addr));
}
__device__ __forceinline__ ull lds64(unsigned addr) {
    ull v; asm("ld.shared.b64 %0, [%1];" : "=l"(v) : "r"(addr)); return v;
}
__device__ __forceinline__ void mbar_init(unsigned addr, unsigned cnt) {
    asm volatile("mbarrier.init.shared.b64 [%0], %1;" :: "r"(addr), "r"(cnt) : "memory");
}
__device__ __forceinline__ void mbar_expect_tx(unsigned addr, unsigned bytes) {
    asm volatile("mbarrier.arrive.expect_tx.shared.b64 _, [%0], %1;"
                 :: "r"(addr), "r"(bytes) : "memory");
}
__device__ __forceinline__ void bulk_g2s(unsigned sdst, const void* gsrc,
                                         unsigned bytes, unsigned mbar) {
    asm volatile("cp.async.bulk.shared::cluster.global.mbarrier::complete_tx::bytes "
                 "[%0], [%1], %2, [%3];"
                 :: "r"(sdst), "l"(gsrc), "r"(bytes), "r"(mbar) : "memory");
}
__device__ __forceinline__ void mbar_wait(unsigned addr, unsigned parity) {
    unsigned done;
    asm volatile(
        "{\n\t.reg .pred p;\n\t"
        "mbarrier.try_wait.parity.acquire.cta.shared::cta.b64 p, [%1], %2;\n\t"
        "selp.b32 %0, 1, 0, p;\n\t}"
        : "=r"(done) : "r"(addr), "r"(parity) : "memory");
    if (!done) {
        asm volatile(
            "{\n\t.reg .pred P1;\n\t"
            "WL_%=:\n\t"
            "mbarrier.try_wait.parity.acquire.cta.shared::cta.b64 P1, [%0], %1, 0x989680;\n\t"
            "@P1 bra.uni WD_%=;\n\t"
            "bra.uni WL_%=;\n\t"
            "WD_%=:\n\t}"
            :: "r"(addr), "r"(parity) : "memory");
    }
}

// symmetric 3x3 inverse of (S + eps*I)
__device__ __forceinline__ void inv3sym(const float* __restrict__ S,
                                        float& i00, float& i01, float& i02,
                                        float& i11, float& i12, float& i22) {
    float s00 = S[0] + EPSF, s01 = S[1], s02 = S[2];
    float s11 = S[4] + EPSF, s12 = S[5];
    float s22 = S[8] + EPSF;
    float c00 = s11 * s22 - s12 * s12;
    float c01 = s02 * s12 - s01 * s22;
    float c02 = s01 * s12 - s02 * s11;
    float c11 = s00 * s22 - s02 * s02;
    float c12 = s01 * s02 - s00 * s12;
    float c22 = s00 * s11 - s01 * s01;
    float det = s00 * c00 + s01 * c01 + s02 * c02;
    float id  = 1.0f / det;
    i00 = c00 * id; i01 = c01 * id; i02 = c02 * id;
    i11 = c11 * id; i12 = c12 * id; i22 = c22 * id;
}

__global__ void __launch_bounds__(NTHR, 3)
loss_kernel(const float* __restrict__ muC, const float* __restrict__ SC,
            const float* __restrict__ muP, const float* __restrict__ SP,
            const float* __restrict__ A,   const float* __restrict__ mask,
            float* __restrict__ out)
{
    extern __shared__ __align__(128) char smem[];
    float* shF   = (float*)(smem + SH_F);
    float* redP  = (float*)(smem + SH_REDP);
    float* redC  = (float*)(smem + SH_REDC);
    float* sMask = (float*)(smem + SH_MASK);
    int*   sLast = (int*)  (smem + SH_LAST);

    const int b   = blockIdx.y;
    const int n0  = blockIdx.x * NT;
    const int tid = threadIdx.x;
    const int k0  = 2 * tid;
    unsigned sbase = (unsigned)__cvta_generic_to_shared(smem);

    // ---- kick off TMA bulk loads of the 64KB A block (4 x 16KB chunks) ----
    if (tid == 0) {
#pragma unroll
        for (int c = 0; c < NCHUNK; c++) mbar_init(sbase + SH_MBAR + 8 * c, 1);
        asm volatile("fence.proxy.async.shared::cta;" ::: "memory");
        const char* gA = (const char*)(A + ((size_t)b * N_ + n0) * K_);
#pragma unroll
        for (int c = 0; c < NCHUNK; c++) {
            unsigned mb = sbase + SH_MBAR + 8 * c;
            mbar_expect_tx(mb, CHUNK_BYTES);
            bulk_g2s(sbase + SH_A + c * CHUNK_BYTES, gA + c * CHUNK_BYTES,
                     CHUNK_BYTES, mb);
        }
    }

    // ---- parent-pair features, packed {k0, k1} (overlaps TMA) ----
    float a00, a01, a02, a11, a12, a22;
    float b00, b01, b02, b11, b12, b22;
    inv3sym(SP + (size_t)(b * K_ + k0) * 9,     a00, a01, a02, a11, a12, a22);
    inv3sym(SP + (size_t)(b * K_ + k0 + 1) * 9, b00, b01, b02, b11, b12, b22);
    const float* mpA = muP + (size_t)(b * K_ + k0) * 3;
    const float* mpB = muP + (size_t)(b * K_ + k0 + 1) * 3;
    ull Pn0  = pack2(-mpA[0], -mpB[0]);
    ull Pn1  = pack2(-mpA[1], -mpB[1]);
    ull Pn2  = pack2(-mpA[2], -mpB[2]);
    ull PI00 = pack2(a00, b00);
    ull PI11 = pack2(a11, b11);
    ull PI22 = pack2(a22, b22);
    ull PI01 = pack2(2.f * a01, 2.f * b01);
    ull PI02 = pack2(2.f * a02, 2.f * b02);
    ull PI12 = pack2(2.f * a12, 2.f * b12);

    // ---- child features -> shared, duplicated {v,v} ----
    if (tid < NT) {
        int n = n0 + tid;
        float j00, j01, j02, j11, j12, j22;
        inv3sym(SC + (size_t)(b * N_ + n) * 9, j00, j01, j02, j11, j12, j22);
        const float* mc = muC + (size_t)(b * N_ + n) * 3;
        float m = mask[b * N_ + n];
        float* d = &shF[tid * 20];
        d[0]  = mc[0];      d[1]  = mc[0];
        d[2]  = mc[1];      d[3]  = mc[1];
        d[4]  = mc[2];      d[5]  = mc[2];
        d[6]  = j00;        d[7]  = j00;
        d[8]  = j11;        d[9]  = j11;
        d[10] = j22;        d[11] = j22;
        d[12] = 2.f * j01;  d[13] = 2.f * j01;
        d[14] = 2.f * j02;  d[15] = 2.f * j02;
        d[16] = 2.f * j12;  d[17] = 2.f * j12;
        d[18] = m;          d[19] = m;
    }
    __syncthreads();

    // block mask partial: warp 0, lane i owns child i
    if (tid < 32) {
        float m = shF[tid * 20 + 18];
#pragma unroll
        for (int off = 16; off; off >>= 1)
            m += __shfl_down_sync(0xffffffffu, m, off);
        if (tid == 0) *sMask = m;
    }

    unsigned fbase = sbase + SH_F;
    unsigned abase = sbase + SH_A + tid * 8;

    ull accP = 0ull, accC = 0ull;

#pragma unroll 8
    for (int n = 0; n < NT; ++n) {
        if ((n & (CHUNK_ROWS - 1)) == 0)
            mbar_wait(sbase + SH_MBAR + 8 * (n / CHUNK_ROWS), 0);

        ull araw = lds64(abase + n * ROWB);   // {A(n,k0), A(n,k1)} packed

        unsigned ad = fbase + n * 80;
        ull Fc0, Fc1, Fc2, FJ00, FJ11, FJ22, FJ01, FJ02, FJ12, Fm;
        lds2(ad,      Fc0,  Fc1 );
        lds2(ad + 16, Fc2,  FJ00);
        lds2(ad + 32, FJ11, FJ22);
        lds2(ad + 48, FJ01, FJ02);
        lds2(ad + 64, FJ12, Fm  );

        ull d0 = add2(Fc0, Pn0);
        ull d1 = add2(Fc1, Pn1);
        ull d2 = add2(Fc2, Pn2);

        ull dd, mp, mc;
        dd = mul2(d0, d0);
        mp = mul2(dd, PI00);      mc = mul2(dd, FJ00);
        dd = mul2(d1, d1);
        mp = fma2(dd, PI11, mp);  mc = fma2(dd, FJ11, mc);
        dd = mul2(d2, d2);
        mp = fma2(dd, PI22, mp);  mc = fma2(dd, FJ22, mc);
        dd = mul2(d0, d1);
        mp = fma2(dd, PI01, mp);  mc = fma2(dd, FJ01, mc);
        dd = mul2(d0, d2);
        mp = fma2(dd, PI02, mp);  mc = fma2(dd, FJ02, mc);
        dd = mul2(d1, d2);
        mp = fma2(dd, PI12, mp);  mc = fma2(dd, FJ12, mc);

        ull am = mul2(araw, Fm);   // {A,A} * mask
        accP = fma2(am, mp, accP);
        accC = fma2(am, mc, accC);
    }

    // ---- in-block reduction ----
    float2 vP = unpack2(accP), vC = unpack2(accC);
    float sp = vP.x + vP.y;
    float sc = vC.x + vC.y;
#pragma unroll
    for (int off = 16; off; off >>= 1) {
        sp += __shfl_down_sync(0xffffffffu, sp, off);
        sc += __shfl_down_sync(0xffffffffu, sc, off);
    }
    int wid = tid >> 5, lane = tid & 31;
    if (lane == 0) { redP[wid] = sp; redC[wid] = sc; }
    __syncthreads();

    const int bid = blockIdx.y * gridDim.x + blockIdx.x;
    if (tid == 0) {
        float tp = 0.f, tc = 0.f;
#pragma unroll
        for (int i = 0; i < 8; i++) { tp += redP[i]; tc += redC[i]; }
        g_blkP[bid] = (double)tp;
        g_blkC[bid] = (double)tc;
        g_blkM[bid] = *sMask;
        __threadfence();
        unsigned t = atomicInc(&g_cnt, GRID_TOTAL - 1);
        *sLast = (t == GRID_TOTAL - 1);
    }
    __syncthreads();

    // ---- last block: final reduction + output ----
    if (*sLast) {
        __threadfence();
        __shared__ double fP[8], fC[8];
        __shared__ float  fM[8];
        double p = g_blkP[tid] + g_blkP[tid + NTHR];   // 512 slots
        double c = g_blkC[tid] + g_blkC[tid + NTHR];
        float  m = g_blkM[tid] + g_blkM[tid + NTHR];
#pragma unroll
        for (int off = 16; off; off >>= 1) {
            p += __shfl_down_sync(0xffffffffu, p, off);
            c += __shfl_down_sync(0xffffffffu, c, off);
            m += __shfl_down_sync(0xffffffffu, m, off);
        }
        if (lane == 0) { fP[wid] = p; fC[wid] = c; fM[wid] = m; }
        __syncthreads();
        if (tid == 0) {
            double tp = 0.0, tc = 0.0;
            float  tm = 0.f;
#pragma unroll
            for (int i = 0; i < 8; i++) { tp += fP[i]; tc += fC[i]; tm += fM[i]; }
            double denom = (tm > 1.f) ? (double)tm : 1.0;
            out[0] = (float)((tp + tc) / denom);  // final_loss
            out[1] = (float)(tp / denom);          // dist_p_m
            out[2] = (float)(tc / denom);          // dist_c_m
        }
    }
}

extern "C" void kernel_launch(void* const* d_in, const int* in_sizes, int n_in,
                              void* d_out, int out_size) {
    const float* muC  = (const float*)d_in[0];
    const float* SC   = (const float*)d_in[1];
    const float* muP  = (const float*)d_in[2];
    const float* SP   = (const float*)d_in[3];
    const float* A    = (const float*)d_in[4];
    const float* mask = (const float*)d_in[5];

    static int configured = -1;
    if (configured < 0) {
        cudaFuncSetAttribute(loss_kernel,
                             cudaFuncAttributeMaxDynamicSharedMemorySize, SMEM_TOTAL);
        configured = 1;
    }
    dim3 grid(GRID_X, B_);
    loss_kernel<<<grid, NTHR, SMEM_TOTAL>>>(muC, SC, muP, SP, A, mask, (float*)d_out);
}